// round 1
// baseline (speedup 1.0000x reference)
#include <cuda_runtime.h>
#include <math.h>

// MidGCN on GB300 — algebraically restructured:
//   adj_f = 0.5*I - 0.5*P - P^2,  P = DAD = d_row[:,None]*adj*d_col[None,:]
//   layer1: H = relu(0.5*X1 - 0.5*P@X1 - P@(P@X1)),  X1 = x@W1
//   layer2: out = log_softmax(0.5*Z - 0.5*P@Z - P@(P@Z) + b2), Z = H@W2
// P@M is computed as d_row ∘ (adj @ (d_col ∘ M)) — DAD never materialized,
// adj_f never materialized (saves the 1.1 TFLOP 8192^3 matmul).

#define NROWS 8192
#define NFEATD 512
#define NHIDD 256

// ---------------- scratch (device globals; no allocations allowed) ----------
__device__ float g_rowsum[NROWS];
__device__ float g_colpart[32 * NROWS];
__device__ float g_drow[NROWS];
__device__ float g_dcol[NROWS];
__device__ float g_X1[NROWS * NHIDD];
__device__ float g_T1[NROWS * NHIDD];
__device__ float g_H [NROWS * NHIDD];
__device__ float2 g_Z  [NROWS];
__device__ float2 g_Zc [NROWS];
__device__ float2 g_U1 [NROWS];
__device__ float2 g_U1c[NROWS];

// ---------------- row sums: one warp per row, float4 loads ------------------
__global__ void rowsum_kernel(const float* __restrict__ adj, float* __restrict__ rowsum) {
    int warp = threadIdx.x >> 5, lane = threadIdx.x & 31;
    int row = blockIdx.x * 8 + warp;
    const float4* rp = (const float4*)(adj + (size_t)row * NROWS);
    float s = 0.f;
    for (int i = lane; i < NROWS / 4; i += 32) {
        float4 v = rp[i];
        s += (v.x + v.y) + (v.z + v.w);
    }
    #pragma unroll
    for (int o = 16; o > 0; o >>= 1) s += __shfl_xor_sync(0xffffffffu, s, o);
    if (lane == 0) rowsum[row] = s;
}

// ---------------- col partial sums: deterministic (no float atomics) --------
__global__ void colpart_kernel(const float* __restrict__ adj, float* __restrict__ part) {
    int c = blockIdx.x * 256 + threadIdx.x;
    int r0 = blockIdx.y * 256;
    float s = 0.f;
    #pragma unroll 8
    for (int r = r0; r < r0 + 256; r++) s += adj[(size_t)r * NROWS + c];
    part[blockIdx.y * NROWS + c] = s;
}

// ---------------- d_row / d_col = sum^-0.5 (inf -> 0) -----------------------
__global__ void dscale_kernel(const float* __restrict__ rowsum, const float* __restrict__ part,
                              float* __restrict__ drow, float* __restrict__ dcol) {
    int i = blockIdx.x * 256 + threadIdx.x;
    float rs = rowsum[i];
    drow[i] = rs > 0.f ? rsqrtf(rs) : 0.f;
    float cs = 0.f;
    #pragma unroll
    for (int p = 0; p < 32; p++) cs += part[p * NROWS + i];
    dcol[i] = cs > 0.f ? rsqrtf(cs) : 0.f;
}

// ---------------- SGEMM: C[M,N] = epilogue(A[M,K] @ (colScale ∘ B[K,N])) ----
// BM=128, BN=64, BK=16, 256 threads, 8x4 microtile.
// MODE 0: C = acc                         (X1 = x @ W1)
// MODE 1: C = drow[m]*acc                 (T1 = P @ X1)
// MODE 2: C = relu(0.5*aux1 - 0.5*aux2 - drow[m]*acc)   (H, fused T2 epilogue)
template<int MODE>
__global__ __launch_bounds__(256, 2)
void sgemm_kernel(const float* __restrict__ A, const float* __restrict__ B,
                  float* __restrict__ C, int K, int lda, int ldb, int ldc,
                  const float* __restrict__ colScale,
                  const float* __restrict__ rowScale,
                  const float* __restrict__ aux1,
                  const float* __restrict__ aux2) {
    const int BM = 128, BN = 64, BK = 16;
    __shared__ float As[BK][BM];   // transposed A tile
    __shared__ float Bs[BK][BN];

    int tid = threadIdx.x;
    int tx = tid & 15;          // N direction (TN=4 -> 64)
    int ty = tid >> 4;          // M direction (TM=8 -> 128)
    int blockM = blockIdx.y * BM;
    int blockN = blockIdx.x * BN;

    float acc[8][4];
    #pragma unroll
    for (int i = 0; i < 8; i++)
        #pragma unroll
        for (int j = 0; j < 4; j++) acc[i][j] = 0.f;

    int b_row = tid >> 4;       // 0..15 (k within tile)
    int b_c4  = tid & 15;       // 0..15 (float4 column)

    for (int k0 = 0; k0 < K; k0 += BK) {
        // A tile: 128x16 = 512 float4 slots, 2 per thread, transpose into smem
        #pragma unroll
        for (int s = 0; s < 2; s++) {
            int slot = tid + s * 256;
            int row = slot >> 2;
            int c4  = slot & 3;
            float4 a = *(const float4*)&A[(size_t)(blockM + row) * lda + k0 + c4 * 4];
            As[c4 * 4 + 0][row] = a.x;
            As[c4 * 4 + 1][row] = a.y;
            As[c4 * 4 + 2][row] = a.z;
            As[c4 * 4 + 3][row] = a.w;
        }
        // B tile: 16x64, one float4 per thread; fold d_col here
        {
            float4 b = *(const float4*)&B[(size_t)(k0 + b_row) * ldb + blockN + b_c4 * 4];
            if (MODE != 0) {
                float s = colScale[k0 + b_row];
                b.x *= s; b.y *= s; b.z *= s; b.w *= s;
            }
            *(float4*)&Bs[b_row][b_c4 * 4] = b;
        }
        __syncthreads();
        #pragma unroll
        for (int k = 0; k < BK; k++) {
            float4 a0 = *(const float4*)&As[k][ty * 8];
            float4 a1 = *(const float4*)&As[k][ty * 8 + 4];
            float4 b  = *(const float4*)&Bs[k][tx * 4];
            float am[8] = {a0.x, a0.y, a0.z, a0.w, a1.x, a1.y, a1.z, a1.w};
            float bn[4] = {b.x, b.y, b.z, b.w};
            #pragma unroll
            for (int i = 0; i < 8; i++)
                #pragma unroll
                for (int j = 0; j < 4; j++)
                    acc[i][j] = fmaf(am[i], bn[j], acc[i][j]);
        }
        __syncthreads();
    }

    #pragma unroll
    for (int i = 0; i < 8; i++) {
        int m = blockM + ty * 8 + i;
        float rs = (MODE >= 1) ? rowScale[m] : 1.f;
        #pragma unroll
        for (int j = 0; j < 4; j++) {
            int n = blockN + tx * 4 + j;
            size_t idx = (size_t)m * ldc + n;
            float v = acc[i][j];
            if (MODE == 0) {
                C[idx] = v;
            } else if (MODE == 1) {
                C[idx] = rs * v;
            } else {
                float t2 = rs * v;
                float h = 0.5f * aux1[idx] - 0.5f * aux2[idx] - t2;
                C[idx] = h > 0.f ? h : 0.f;
            }
        }
    }
}

// ---------------- Z = H @ W2 (N=2); also Zc = d_col ∘ Z ---------------------
__global__ void zw_kernel(const float* __restrict__ H, const float* __restrict__ W2,
                          const float* __restrict__ dcol,
                          float2* __restrict__ Z, float2* __restrict__ Zc) {
    int warp = threadIdx.x >> 5, lane = threadIdx.x & 31;
    int row = blockIdx.x * 8 + warp;
    const float* h = H + (size_t)row * NHIDD;
    float a0 = 0.f, a1 = 0.f;
    for (int k = lane; k < NHIDD; k += 32) {
        float hv = h[k];
        a0 = fmaf(hv, W2[2 * k], a0);
        a1 = fmaf(hv, W2[2 * k + 1], a1);
    }
    #pragma unroll
    for (int o = 16; o > 0; o >>= 1) {
        a0 += __shfl_xor_sync(0xffffffffu, a0, o);
        a1 += __shfl_xor_sync(0xffffffffu, a1, o);
    }
    if (lane == 0) {
        Z[row] = make_float2(a0, a1);
        float dc = dcol[row];
        Zc[row] = make_float2(dc * a0, dc * a1);
    }
}

// ---------------- U = d_row ∘ (adj @ V), V is [8192, 2] ---------------------
// FINAL=0: write U1 and U1c = d_col ∘ U1
// FINAL=1: fuse: out = log_softmax(0.5*Z - 0.5*U1 - U2 + b2)
template<int FINAL>
__global__ void pv_kernel(const float* __restrict__ adj, const float2* __restrict__ V,
                          const float* __restrict__ drow, const float* __restrict__ dcol,
                          const float2* __restrict__ Z, const float2* __restrict__ U1,
                          const float* __restrict__ b2,
                          float2* __restrict__ outU, float2* __restrict__ outUc,
                          float* __restrict__ out) {
    int warp = threadIdx.x >> 5, lane = threadIdx.x & 31;
    int row = blockIdx.x * 8 + warp;
    const float4* ap = (const float4*)(adj + (size_t)row * NROWS);
    float ax = 0.f, ay = 0.f;
    for (int i = lane; i < NROWS / 4; i += 32) {
        float4 a = ap[i];
        int k = i * 4;
        float2 v0 = V[k], v1 = V[k + 1], v2 = V[k + 2], v3 = V[k + 3];
        ax += a.x * v0.x + a.y * v1.x + a.z * v2.x + a.w * v3.x;
        ay += a.x * v0.y + a.y * v1.y + a.z * v2.y + a.w * v3.y;
    }
    #pragma unroll
    for (int o = 16; o > 0; o >>= 1) {
        ax += __shfl_xor_sync(0xffffffffu, ax, o);
        ay += __shfl_xor_sync(0xffffffffu, ay, o);
    }
    if (lane == 0) {
        float dr = drow[row];
        float ux = dr * ax, uy = dr * ay;
        if (FINAL == 0) {
            outU[row] = make_float2(ux, uy);
            float dc = dcol[row];
            outUc[row] = make_float2(dc * ux, dc * uy);
        } else {
            float2 z = Z[row];
            float2 u1 = U1[row];
            float l0 = 0.5f * z.x - 0.5f * u1.x - ux + b2[0];
            float l1 = 0.5f * z.y - 0.5f * u1.y - uy + b2[1];
            float mx = fmaxf(l0, l1);
            float lse = mx + logf(expf(l0 - mx) + expf(l1 - mx));
            out[2 * row + 0] = l0 - lse;
            out[2 * row + 1] = l1 - lse;
        }
    }
}

// ---------------- launcher --------------------------------------------------
extern "C" void kernel_launch(void* const* d_in, const int* in_sizes, int n_in,
                              void* d_out, int out_size) {
    const float* x   = (const float*)d_in[0];   // [8192, 512]
    const float* adj = (const float*)d_in[1];   // [8192, 8192]
    const float* W1  = (const float*)d_in[2];   // [512, 256]
    const float* W2  = (const float*)d_in[3];   // [256, 2]
    const float* b2  = (const float*)d_in[4];   // [2]
    float* out = (float*)d_out;                 // [8192, 2]

    float *rowsum, *colpart, *drow, *dcol, *X1, *T1, *H;
    float2 *Z, *Zc, *U1, *U1c;
    cudaGetSymbolAddress((void**)&rowsum,  g_rowsum);
    cudaGetSymbolAddress((void**)&colpart, g_colpart);
    cudaGetSymbolAddress((void**)&drow,    g_drow);
    cudaGetSymbolAddress((void**)&dcol,    g_dcol);
    cudaGetSymbolAddress((void**)&X1,      g_X1);
    cudaGetSymbolAddress((void**)&T1,      g_T1);
    cudaGetSymbolAddress((void**)&H,       g_H);
    cudaGetSymbolAddress((void**)&Z,       g_Z);
    cudaGetSymbolAddress((void**)&Zc,      g_Zc);
    cudaGetSymbolAddress((void**)&U1,      g_U1);
    cudaGetSymbolAddress((void**)&U1c,     g_U1c);

    // degree scalings
    rowsum_kernel<<<NROWS / 8, 256>>>(adj, rowsum);
    colpart_kernel<<<dim3(NROWS / 256, 32), 256>>>(adj, colpart);
    dscale_kernel<<<NROWS / 256, 256>>>(rowsum, colpart, drow, dcol);

    // X1 = x @ W1
    sgemm_kernel<0><<<dim3(NHIDD / 64, NROWS / 128), 256>>>(
        x, W1, X1, NFEATD, NFEATD, NHIDD, NHIDD, nullptr, nullptr, nullptr, nullptr);

    // T1 = P @ X1
    sgemm_kernel<1><<<dim3(NHIDD / 64, NROWS / 128), 256>>>(
        adj, X1, T1, NROWS, NROWS, NHIDD, NHIDD, dcol, drow, nullptr, nullptr);

    // H = relu(0.5*X1 - 0.5*T1 - P@T1)   (T2 epilogue fused)
    sgemm_kernel<2><<<dim3(NHIDD / 64, NROWS / 128), 256>>>(
        adj, T1, H, NROWS, NROWS, NHIDD, NHIDD, dcol, drow, X1, T1);

    // Z = H @ W2 ; Zc = d_col ∘ Z
    zw_kernel<<<NROWS / 8, 256>>>(H, W2, dcol, Z, Zc);

    // U1 = P @ Z ; U1c = d_col ∘ U1
    pv_kernel<0><<<NROWS / 8, 256>>>(adj, Zc, drow, dcol,
                                     nullptr, nullptr, nullptr, U1, U1c, nullptr);

    // out = log_softmax(0.5*Z - 0.5*U1 - P@U1 + b2)
    pv_kernel<1><<<NROWS / 8, 256>>>(adj, U1c, drow, dcol,
                                     Z, U1, b2, nullptr, nullptr, out);
}

// round 3
// speedup vs baseline: 2.3943x; 2.3943x over previous
#include <cuda_runtime.h>
#include <cuda_bf16.h>
#include <math.h>
#include <stdint.h>

// MidGCN on GB300 (compute_103 PTX => no tcgen05; use mma.sync bf16 HMMA):
//   adj_f = 0.5*I - 0.5*P - P^2,  P = drow ∘ adj ∘ dcol
//   layer1: H = relu(0.5*X1 - 0.5*T1 - P@T1),  X1 = x@W1, T1 = P@X1
//   layer2: out = log_softmax(0.5*Z - 0.5*U1 - P@(dcol∘U1) + b2), Z = H@W2
// Big GEMMs (P @ [8192x256]) use 3-way bf16 split (hi*hi + hi*lo + lo*hi)
// on tensor cores for ~fp32 precision.

#define NROWS 8192
#define NHIDD 256
#define NFEATD 512

// ---------------- scratch (device globals) ----------------------------------
__device__ float g_rowsum[NROWS];
__device__ float g_colpart[32 * NROWS];
__device__ float g_drow[NROWS];
__device__ float g_dcol[NROWS];
__device__ float g_X1[NROWS * NHIDD];
__device__ float g_T1[NROWS * NHIDD];
__device__ float g_ACC[NROWS * NHIDD];
__device__ unsigned short g_Phi[(size_t)NROWS * NROWS];
__device__ unsigned short g_Plo[(size_t)NROWS * NROWS];
__device__ unsigned short g_Bt1hi[NHIDD * NROWS];
__device__ unsigned short g_Bt1lo[NHIDD * NROWS];
__device__ unsigned short g_Bt2hi[NHIDD * NROWS];
__device__ unsigned short g_Bt2lo[NHIDD * NROWS];
__device__ float2 g_Z  [NROWS];
__device__ float2 g_Zc [NROWS];
__device__ float2 g_U1 [NROWS];
__device__ float2 g_U1c[NROWS];

// ---------------- helpers ----------------------------------------------------
__device__ __forceinline__ uint32_t smem_u32(const void* p) {
    return (uint32_t)__cvta_generic_to_shared(p);
}
__device__ __forceinline__ void cp16(uint32_t s, const void* g) {
    asm volatile("cp.async.cg.shared.global [%0], [%1], 16;"
                 :: "r"(s), "l"(__cvta_generic_to_global(g)) : "memory");
}
#define CP_COMMIT() asm volatile("cp.async.commit_group;" ::: "memory")
#define CP_WAIT(n)  asm volatile("cp.async.wait_group %0;" :: "n"(n) : "memory")

__device__ __forceinline__ void ldmx4(uint32_t& r0, uint32_t& r1, uint32_t& r2, uint32_t& r3,
                                      uint32_t addr) {
    asm volatile("ldmatrix.sync.aligned.m8n8.x4.shared.b16 {%0,%1,%2,%3}, [%4];"
                 : "=r"(r0), "=r"(r1), "=r"(r2), "=r"(r3) : "r"(addr));
}
__device__ __forceinline__ void mma_bf16(float* d, const uint32_t* a, const uint32_t* b) {
    asm volatile(
        "mma.sync.aligned.m16n8k16.row.col.f32.bf16.bf16.f32 "
        "{%0,%1,%2,%3}, {%4,%5,%6,%7}, {%8,%9}, {%0,%1,%2,%3};"
        : "+f"(d[0]), "+f"(d[1]), "+f"(d[2]), "+f"(d[3])
        : "r"(a[0]), "r"(a[1]), "r"(a[2]), "r"(a[3]), "r"(b[0]), "r"(b[1]));
}
__device__ __forceinline__ uint32_t sw128(uint32_t off) {
    return off ^ ((off >> 3) & 0x70);
}

// ---------------- degree scalings --------------------------------------------
__global__ void rowsum_kernel(const float* __restrict__ adj, float* __restrict__ rowsum) {
    int warp = threadIdx.x >> 5, lane = threadIdx.x & 31;
    int row = blockIdx.x * 8 + warp;
    const float4* rp = (const float4*)(adj + (size_t)row * NROWS);
    float s = 0.f;
    for (int i = lane; i < NROWS / 4; i += 32) {
        float4 v = rp[i];
        s += (v.x + v.y) + (v.z + v.w);
    }
    #pragma unroll
    for (int o = 16; o > 0; o >>= 1) s += __shfl_xor_sync(0xffffffffu, s, o);
    if (lane == 0) rowsum[row] = s;
}

__global__ void colpart_kernel(const float* __restrict__ adj, float* __restrict__ part) {
    int c = blockIdx.x * 256 + threadIdx.x;
    int r0 = blockIdx.y * 256;
    float s = 0.f;
    #pragma unroll 8
    for (int r = r0; r < r0 + 256; r++) s += adj[(size_t)r * NROWS + c];
    part[blockIdx.y * NROWS + c] = s;
}

__global__ void dscale_kernel(const float* __restrict__ rowsum, const float* __restrict__ part,
                              float* __restrict__ drow, float* __restrict__ dcol) {
    int i = blockIdx.x * 256 + threadIdx.x;
    float rs = rowsum[i];
    drow[i] = rs > 0.f ? rsqrtf(rs) : 0.f;
    float cs = 0.f;
    #pragma unroll
    for (int p = 0; p < 32; p++) cs += part[p * NROWS + i];
    dcol[i] = cs > 0.f ? rsqrtf(cs) : 0.f;
}

// ---------------- P = drow∘adj∘dcol -> bf16 hi/lo ---------------------------
__global__ void convert_adj(const float* __restrict__ adj,
                            const float* __restrict__ drow, const float* __restrict__ dcol,
                            unsigned short* __restrict__ phi, unsigned short* __restrict__ plo) {
    size_t i4 = (size_t)blockIdx.x * 256 + threadIdx.x;
    int row = (int)(i4 >> 11);
    int c4  = (int)(i4 & 2047);
    float4 v = ((const float4*)adj)[i4];
    float dr = drow[row];
    float4 dc = ((const float4*)dcol)[c4];
    float p0 = dr * v.x * dc.x, p1 = dr * v.y * dc.y;
    float p2 = dr * v.z * dc.z, p3 = dr * v.w * dc.w;
    __nv_bfloat16 h0 = __float2bfloat16(p0), h1 = __float2bfloat16(p1);
    __nv_bfloat16 h2 = __float2bfloat16(p2), h3 = __float2bfloat16(p3);
    __nv_bfloat16 l0 = __float2bfloat16(p0 - __bfloat162float(h0));
    __nv_bfloat16 l1 = __float2bfloat16(p1 - __bfloat162float(h1));
    __nv_bfloat16 l2 = __float2bfloat16(p2 - __bfloat162float(h2));
    __nv_bfloat16 l3 = __float2bfloat16(p3 - __bfloat162float(h3));
    uint2 hv, lv;
    hv.x = (uint32_t)__bfloat16_as_ushort(h0) | ((uint32_t)__bfloat16_as_ushort(h1) << 16);
    hv.y = (uint32_t)__bfloat16_as_ushort(h2) | ((uint32_t)__bfloat16_as_ushort(h3) << 16);
    lv.x = (uint32_t)__bfloat16_as_ushort(l0) | ((uint32_t)__bfloat16_as_ushort(l1) << 16);
    lv.y = (uint32_t)__bfloat16_as_ushort(l2) | ((uint32_t)__bfloat16_as_ushort(l3) << 16);
    ((uint2*)phi)[i4] = hv;
    ((uint2*)plo)[i4] = lv;
}

// ---------------- X1 = x @ W1 (fp32 SIMT) + transposed bf16 hi/lo -----------
__global__ __launch_bounds__(256, 2)
void sgemm_x(const float* __restrict__ A, const float* __restrict__ B,
             float* __restrict__ C,
             unsigned short* __restrict__ Bthi, unsigned short* __restrict__ Btlo) {
    const int BM = 128, BK = 16, K = NFEATD;
    __shared__ float As[BK][BM];
    __shared__ float Bs[BK][64];
    int tid = threadIdx.x;
    int tx = tid & 15, ty = tid >> 4;
    int blockM = blockIdx.y * BM, blockN = blockIdx.x * 64;
    float acc[8][4];
    #pragma unroll
    for (int i = 0; i < 8; i++)
        #pragma unroll
        for (int j = 0; j < 4; j++) acc[i][j] = 0.f;
    int b_row = tid >> 4, b_c4 = tid & 15;
    for (int k0 = 0; k0 < K; k0 += BK) {
        #pragma unroll
        for (int s = 0; s < 2; s++) {
            int slot = tid + s * 256;
            int row = slot >> 2, c4 = slot & 3;
            float4 a = *(const float4*)&A[(size_t)(blockM + row) * K + k0 + c4 * 4];
            As[c4 * 4 + 0][row] = a.x; As[c4 * 4 + 1][row] = a.y;
            As[c4 * 4 + 2][row] = a.z; As[c4 * 4 + 3][row] = a.w;
        }
        {
            float4 b = *(const float4*)&B[(size_t)(k0 + b_row) * NHIDD + blockN + b_c4 * 4];
            *(float4*)&Bs[b_row][b_c4 * 4] = b;
        }
        __syncthreads();
        #pragma unroll
        for (int k = 0; k < BK; k++) {
            float4 a0 = *(const float4*)&As[k][ty * 8];
            float4 a1 = *(const float4*)&As[k][ty * 8 + 4];
            float4 b  = *(const float4*)&Bs[k][tx * 4];
            float am[8] = {a0.x, a0.y, a0.z, a0.w, a1.x, a1.y, a1.z, a1.w};
            float bn[4] = {b.x, b.y, b.z, b.w};
            #pragma unroll
            for (int i = 0; i < 8; i++)
                #pragma unroll
                for (int j = 0; j < 4; j++)
                    acc[i][j] = fmaf(am[i], bn[j], acc[i][j]);
        }
        __syncthreads();
    }
    #pragma unroll
    for (int i = 0; i < 8; i++) {
        int m = blockM + ty * 8 + i;
        #pragma unroll
        for (int j = 0; j < 4; j++)
            C[(size_t)m * NHIDD + blockN + tx * 4 + j] = acc[i][j];
    }
    #pragma unroll
    for (int j = 0; j < 4; j++) {
        int n = blockN + tx * 4 + j;
        uint32_t hp[4], lp[4];
        #pragma unroll
        for (int p = 0; p < 4; p++) {
            float v0 = acc[2 * p][j], v1 = acc[2 * p + 1][j];
            __nv_bfloat16 h0 = __float2bfloat16(v0), h1 = __float2bfloat16(v1);
            __nv_bfloat16 l0 = __float2bfloat16(v0 - __bfloat162float(h0));
            __nv_bfloat16 l1 = __float2bfloat16(v1 - __bfloat162float(h1));
            hp[p] = (uint32_t)__bfloat16_as_ushort(h0) | ((uint32_t)__bfloat16_as_ushort(h1) << 16);
            lp[p] = (uint32_t)__bfloat16_as_ushort(l0) | ((uint32_t)__bfloat16_as_ushort(l1) << 16);
        }
        size_t o = (size_t)n * NROWS + blockM + ty * 8;
        *(uint4*)&Bthi[o] = make_uint4(hp[0], hp[1], hp[2], hp[3]);
        *(uint4*)&Btlo[o] = make_uint4(lp[0], lp[1], lp[2], lp[3]);
    }
}

// ---------------- HMMA GEMM: C[64x256 per CTA] = P @ Bt^T (3-way split) -----
// BM=64, BN=256, BK=64, 2-stage cp.async, SW128 smem, 8 warps (2M x 4N),
// warp tile 32x64, mma m16n8k16 bf16.
#define GK 64
#define STG_A  8192            // 64 rows * 128B (one operand)
#define STG_B  32768           // 256 rows * 128B
#define STG_BYTES (2*STG_A + 2*STG_B)   // 81920
#define GEMM_SMEM (2 * STG_BYTES)       // 163840

__global__ __launch_bounds__(256, 1)
void gemm3(const unsigned short* __restrict__ Ahi_g, const unsigned short* __restrict__ Alo_g,
           const unsigned short* __restrict__ Bhi_g, const unsigned short* __restrict__ Blo_g,
           float* __restrict__ C) {
    extern __shared__ __align__(1024) char smem[];
    const int tid = threadIdx.x, lane = tid & 31, wid = tid >> 5;
    const int wm = wid >> 2;          // 0..1
    const int wn = wid & 3;           // 0..3
    const int blockM = blockIdx.x * 64;
    const uint32_t sbase = smem_u32(smem);

    const unsigned short* Ahi = Ahi_g + (size_t)blockM * NROWS;
    const unsigned short* Alo = Alo_g + (size_t)blockM * NROWS;

    float d[2][8][4];
    #pragma unroll
    for (int mt = 0; mt < 2; mt++)
        #pragma unroll
        for (int nt = 0; nt < 8; nt++)
            #pragma unroll
            for (int e = 0; e < 4; e++) d[mt][nt][e] = 0.f;

    auto load_stage = [&](int it, uint32_t stg) {
        int k0 = it * GK;
        // Ahi: rows 0..63, 8 chunks of 16B each
        for (int idx = tid; idx < 512; idx += 256) {
            int row = idx >> 3, g = idx & 7;
            cp16(stg + sw128((uint32_t)(row * 128 + g * 16)),
                 Ahi + (size_t)row * NROWS + k0 + g * 8);
        }
        for (int idx = tid; idx < 512; idx += 256) {
            int row = idx >> 3, g = idx & 7;
            cp16(stg + STG_A + sw128((uint32_t)(row * 128 + g * 16)),
                 Alo + (size_t)row * NROWS + k0 + g * 8);
        }
        for (int idx = tid; idx < 2048; idx += 256) {
            int row = idx >> 3, g = idx & 7;
            cp16(stg + 2 * STG_A + sw128((uint32_t)(row * 128 + g * 16)),
                 Bhi_g + (size_t)row * NROWS + k0 + g * 8);
        }
        for (int idx = tid; idx < 2048; idx += 256) {
            int row = idx >> 3, g = idx & 7;
            cp16(stg + 2 * STG_A + STG_B + sw128((uint32_t)(row * 128 + g * 16)),
                 Blo_g + (size_t)row * NROWS + k0 + g * 8);
        }
    };

    // per-thread ldmatrix offsets
    const int rowA = wm * 32 + (lane & 15);            // + mt*16
    const int kbA  = (lane >> 4) * 16;
    const int rowB = wn * 64 + (lane & 7) + ((lane >> 4) & 1) * 8;  // + p*16
    const int kbB  = ((lane >> 3) & 1) * 16;

    const int NIT = NROWS / GK;   // 128
    load_stage(0, sbase);
    CP_COMMIT();

    for (int it = 0; it < NIT; ++it) {
        uint32_t stg = sbase + (uint32_t)(it & 1) * STG_BYTES;
        if (it + 1 < NIT) {
            load_stage(it + 1, sbase + (uint32_t)((it + 1) & 1) * STG_BYTES);
            CP_COMMIT();
            CP_WAIT(1);
        } else {
            CP_WAIT(0);
        }
        __syncthreads();

        const uint32_t sAhi = stg, sAlo = stg + STG_A;
        const uint32_t sBhi = stg + 2 * STG_A, sBlo = stg + 2 * STG_A + STG_B;

        #pragma unroll
        for (int ks = 0; ks < 4; ks++) {
            uint32_t ah[2][4], al[2][4];
            #pragma unroll
            for (int mt = 0; mt < 2; mt++) {
                uint32_t off = sw128((uint32_t)((rowA + mt * 16) * 128 + ks * 32 + kbA));
                ldmx4(ah[mt][0], ah[mt][1], ah[mt][2], ah[mt][3], sAhi + off);
                ldmx4(al[mt][0], al[mt][1], al[mt][2], al[mt][3], sAlo + off);
            }
            uint32_t bh[8][2], bl[8][2];
            #pragma unroll
            for (int p = 0; p < 4; p++) {
                uint32_t off = sw128((uint32_t)((rowB + p * 16) * 128 + ks * 32 + kbB));
                ldmx4(bh[2*p][0], bh[2*p][1], bh[2*p+1][0], bh[2*p+1][1], sBhi + off);
                ldmx4(bl[2*p][0], bl[2*p][1], bl[2*p+1][0], bl[2*p+1][1], sBlo + off);
            }
            #pragma unroll
            for (int mt = 0; mt < 2; mt++)
                #pragma unroll
                for (int nt = 0; nt < 8; nt++) {
                    mma_bf16(d[mt][nt], ah[mt], bh[nt]);
                    mma_bf16(d[mt][nt], ah[mt], bl[nt]);
                    mma_bf16(d[mt][nt], al[mt], bh[nt]);
                }
        }
        __syncthreads();
    }

    // store C: row m = blockM + wm*32 + mt*16 + (lane>>2) (+8), col = wn*64 + nt*8 + (lane&3)*2
    const int q = lane >> 2, c2 = (lane & 3) * 2;
    #pragma unroll
    for (int mt = 0; mt < 2; mt++) {
        int m0 = blockM + wm * 32 + mt * 16 + q;
        #pragma unroll
        for (int nt = 0; nt < 8; nt++) {
            int col = wn * 64 + nt * 8 + c2;
            *(float2*)&C[(size_t)m0 * NHIDD + col]       = make_float2(d[mt][nt][0], d[mt][nt][1]);
            *(float2*)&C[(size_t)(m0 + 8) * NHIDD + col] = make_float2(d[mt][nt][2], d[mt][nt][3]);
        }
    }
}

// ---------------- T1 -> Bt2 (transpose + bf16 hi/lo split) ------------------
__global__ void trans_split(const float* __restrict__ T1,
                            unsigned short* __restrict__ hi, unsigned short* __restrict__ lo) {
    __shared__ float tile[32][33];
    int m0 = blockIdx.x * 32, n0 = blockIdx.y * 32;
    int tx = threadIdx.x, ty = threadIdx.y;   // 32 x 8
    #pragma unroll
    for (int j = 0; j < 4; j++)
        tile[ty + j * 8][tx] = T1[(size_t)(m0 + ty + j * 8) * NHIDD + n0 + tx];
    __syncthreads();
    #pragma unroll
    for (int j = 0; j < 4; j++) {
        int n = n0 + ty + j * 8;
        float v = tile[tx][ty + j * 8];
        __nv_bfloat16 h = __float2bfloat16(v);
        __nv_bfloat16 l = __float2bfloat16(v - __bfloat162float(h));
        size_t o = (size_t)n * NROWS + m0 + tx;
        hi[o] = __bfloat16_as_ushort(h);
        lo[o] = __bfloat16_as_ushort(l);
    }
}

// ---------------- layer-1 epilogue + Z = H@W2 fused -------------------------
__global__ void epi2_kernel(const float* __restrict__ ACC, const float* __restrict__ X1,
                            const float* __restrict__ T1, const float* __restrict__ W2,
                            const float* __restrict__ dcol,
                            float2* __restrict__ Z, float2* __restrict__ Zc) {
    int warp = threadIdx.x >> 5, lane = threadIdx.x & 31;
    int row = blockIdx.x * 8 + warp;
    size_t base = (size_t)row * NHIDD;
    float z0 = 0.f, z1 = 0.f;
    #pragma unroll
    for (int b = 0; b < 2; b++) {
        int n0 = lane * 8 + b * 4;
        float4 av = *(const float4*)&ACC[base + n0];
        float4 xv = *(const float4*)&X1[base + n0];
        float4 tv = *(const float4*)&T1[base + n0];
        float as[4] = {av.x, av.y, av.z, av.w};
        float xs[4] = {xv.x, xv.y, xv.z, xv.w};
        float ts[4] = {tv.x, tv.y, tv.z, tv.w};
        #pragma unroll
        for (int e = 0; e < 4; e++) {
            float h = 0.5f * xs[e] - 0.5f * ts[e] - as[e];
            h = h > 0.f ? h : 0.f;
            int n = n0 + e;
            z0 = fmaf(h, W2[2 * n], z0);
            z1 = fmaf(h, W2[2 * n + 1], z1);
        }
    }
    #pragma unroll
    for (int o = 16; o > 0; o >>= 1) {
        z0 += __shfl_xor_sync(0xffffffffu, z0, o);
        z1 += __shfl_xor_sync(0xffffffffu, z1, o);
    }
    if (lane == 0) {
        Z[row] = make_float2(z0, z1);
        float dc = dcol[row];
        Zc[row] = make_float2(dc * z0, dc * z1);
    }
}

// ---------------- U = drow ∘ (adj @ V), V [8192,2]; FINAL fuses softmax -----
template<int FINAL>
__global__ void pv_kernel(const float* __restrict__ adj, const float2* __restrict__ V,
                          const float* __restrict__ drow, const float* __restrict__ dcol,
                          const float2* __restrict__ Z, const float2* __restrict__ U1,
                          const float* __restrict__ b2,
                          float2* __restrict__ outU, float2* __restrict__ outUc,
                          float* __restrict__ out) {
    int warp = threadIdx.x >> 5, lane = threadIdx.x & 31;
    int row = blockIdx.x * 8 + warp;
    const float4* ap = (const float4*)(adj + (size_t)row * NROWS);
    float ax = 0.f, ay = 0.f;
    for (int i = lane; i < NROWS / 4; i += 32) {
        float4 a = ap[i];
        int k = i * 4;
        float2 v0 = V[k], v1 = V[k + 1], v2 = V[k + 2], v3 = V[k + 3];
        ax += a.x * v0.x + a.y * v1.x + a.z * v2.x + a.w * v3.x;
        ay += a.x * v0.y + a.y * v1.y + a.z * v2.y + a.w * v3.y;
    }
    #pragma unroll
    for (int o = 16; o > 0; o >>= 1) {
        ax += __shfl_xor_sync(0xffffffffu, ax, o);
        ay += __shfl_xor_sync(0xffffffffu, ay, o);
    }
    if (lane == 0) {
        float dr = drow[row];
        float ux = dr * ax, uy = dr * ay;
        if (FINAL == 0) {
            outU[row] = make_float2(ux, uy);
            float dc = dcol[row];
            outUc[row] = make_float2(dc * ux, dc * uy);
        } else {
            float2 z = Z[row];
            float2 u1 = U1[row];
            float l0 = 0.5f * z.x - 0.5f * u1.x - ux + b2[0];
            float l1 = 0.5f * z.y - 0.5f * u1.y - uy + b2[1];
            float mx = fmaxf(l0, l1);
            float lse = mx + logf(expf(l0 - mx) + expf(l1 - mx));
            out[2 * row + 0] = l0 - lse;
            out[2 * row + 1] = l1 - lse;
        }
    }
}

// ---------------- launcher --------------------------------------------------
extern "C" void kernel_launch(void* const* d_in, const int* in_sizes, int n_in,
                              void* d_out, int out_size) {
    const float* x   = (const float*)d_in[0];
    const float* adj = (const float*)d_in[1];
    const float* W1  = (const float*)d_in[2];
    const float* W2  = (const float*)d_in[3];
    const float* b2  = (const float*)d_in[4];
    float* out = (float*)d_out;

    float *rowsum, *colpart, *drow, *dcol, *X1, *T1, *ACC;
    unsigned short *Phi, *Plo, *Bt1hi, *Bt1lo, *Bt2hi, *Bt2lo;
    float2 *Z, *Zc, *U1, *U1c;
    cudaGetSymbolAddress((void**)&rowsum,  g_rowsum);
    cudaGetSymbolAddress((void**)&colpart, g_colpart);
    cudaGetSymbolAddress((void**)&drow,    g_drow);
    cudaGetSymbolAddress((void**)&dcol,    g_dcol);
    cudaGetSymbolAddress((void**)&X1,      g_X1);
    cudaGetSymbolAddress((void**)&T1,      g_T1);
    cudaGetSymbolAddress((void**)&ACC,     g_ACC);
    cudaGetSymbolAddress((void**)&Phi,     g_Phi);
    cudaGetSymbolAddress((void**)&Plo,     g_Plo);
    cudaGetSymbolAddress((void**)&Bt1hi,   g_Bt1hi);
    cudaGetSymbolAddress((void**)&Bt1lo,   g_Bt1lo);
    cudaGetSymbolAddress((void**)&Bt2hi,   g_Bt2hi);
    cudaGetSymbolAddress((void**)&Bt2lo,   g_Bt2lo);
    cudaGetSymbolAddress((void**)&Z,       g_Z);
    cudaGetSymbolAddress((void**)&Zc,      g_Zc);
    cudaGetSymbolAddress((void**)&U1,      g_U1);
    cudaGetSymbolAddress((void**)&U1c,     g_U1c);

    cudaFuncSetAttribute(gemm3, cudaFuncAttributeMaxDynamicSharedMemorySize, GEMM_SMEM);

    // degree scalings
    rowsum_kernel<<<NROWS / 8, 256>>>(adj, rowsum);
    colpart_kernel<<<dim3(NROWS / 256, 32), 256>>>(adj, colpart);
    dscale_kernel<<<NROWS / 256, 256>>>(rowsum, colpart, drow, dcol);

    // X1 = x @ W1 (+ transposed bf16 hi/lo)
    sgemm_x<<<dim3(NHIDD / 64, NROWS / 128), 256>>>(x, W1, X1, Bt1hi, Bt1lo);

    // P -> bf16 hi/lo
    convert_adj<<<(NROWS * (NROWS / 4)) / 256, 256>>>(adj, drow, dcol, Phi, Plo);

    // T1 = P @ X1
    gemm3<<<NROWS / 64, 256, GEMM_SMEM>>>(Phi, Plo, Bt1hi, Bt1lo, T1);

    // Bt2 = T1^T bf16 hi/lo
    trans_split<<<dim3(NROWS / 32, NHIDD / 32), dim3(32, 8)>>>(T1, Bt2hi, Bt2lo);

    // ACC = P @ T1
    gemm3<<<NROWS / 64, 256, GEMM_SMEM>>>(Phi, Plo, Bt2hi, Bt2lo, ACC);

    // H = relu(0.5*X1 - 0.5*T1 - ACC); Z = H@W2; Zc = dcol∘Z
    epi2_kernel<<<NROWS / 8, 256>>>(ACC, X1, T1, W2, dcol, Z, Zc);

    // U1 = P @ Z ; U1c = dcol∘U1
    pv_kernel<0><<<NROWS / 8, 256>>>(adj, Zc, drow, dcol,
                                     nullptr, nullptr, nullptr, U1, U1c, nullptr);

    // out = log_softmax(0.5*Z - 0.5*U1 - P@U1c + b2)
    pv_kernel<1><<<NROWS / 8, 256>>>(adj, U1c, drow, dcol,
                                     Z, U1, b2, nullptr, nullptr, out);
}

// round 4
// speedup vs baseline: 2.7728x; 1.1581x over previous
#include <cuda_runtime.h>
#include <cuda_fp16.h>
#include <math.h>
#include <stdint.h>

// MidGCN on GB300 (compute_103 PTX => mma.sync fp16 HMMA):
//   adj_f = 0.5*I - 0.5*P - P^2,  P = drow ∘ adj ∘ dcol
//   layer1: H = relu(0.5*X1 - 0.5*T1 - P@T1),  X1 = x@W1, T1 = P@X1
//   layer2: out = log_softmax(0.5*Z - 0.5*(P@Z) - P@(P@Z) + b2), Z = H@W2
// Big GEMMs use asymmetric fp16 split: A_fp16 @ (B_hi + B_lo)  (2 MMA products).
// P is stored pre-scaled by 4096 (64*64 folded into drow/dcol) for fp16 range.

#define NROWS 8192
#define NHIDD 256
#define NFEATD 512
#define DESCALE (1.0f / 4096.0f)

// ---------------- scratch (device globals) ----------------------------------
__device__ float g_rowpart[32 * NROWS];
__device__ float g_colpart[64 * NROWS];
__device__ float g_drow[NROWS];
__device__ float g_dcol[NROWS];
__device__ float g_X1[NROWS * NHIDD];
__device__ float g_T1[NROWS * NHIDD];
__device__ float g_ACC[NROWS * NHIDD];
__device__ __half g_Ps[(size_t)NROWS * NROWS];     // P * 4096, fp16
__device__ __half g_xh[NROWS * NFEATD];            // x fp16
__device__ __half g_W1Thi[NHIDD * NFEATD];         // W1^T hi/lo
__device__ __half g_W1Tlo[NHIDD * NFEATD];
__device__ __half g_Bt1hi[NHIDD * NROWS];          // X1^T hi/lo
__device__ __half g_Bt1lo[NHIDD * NROWS];
__device__ __half g_Bt2hi[NHIDD * NROWS];          // T1^T hi/lo
__device__ __half g_Bt2lo[NHIDD * NROWS];
__device__ float2 g_Z [NROWS];
__device__ float2 g_U1[NROWS];

// ---------------- helpers ----------------------------------------------------
__device__ __forceinline__ uint32_t smem_u32(const void* p) {
    return (uint32_t)__cvta_generic_to_shared(p);
}
__device__ __forceinline__ void cp16(uint32_t s, const void* g) {
    asm volatile("cp.async.cg.shared.global [%0], [%1], 16;"
                 :: "r"(s), "l"(__cvta_generic_to_global(g)) : "memory");
}
#define CP_COMMIT() asm volatile("cp.async.commit_group;" ::: "memory")
#define CP_WAIT(n)  asm volatile("cp.async.wait_group %0;" :: "n"(n) : "memory")

__device__ __forceinline__ void ldmx4(uint32_t& r0, uint32_t& r1, uint32_t& r2, uint32_t& r3,
                                      uint32_t addr) {
    asm volatile("ldmatrix.sync.aligned.m8n8.x4.shared.b16 {%0,%1,%2,%3}, [%4];"
                 : "=r"(r0), "=r"(r1), "=r"(r2), "=r"(r3) : "r"(addr));
}
__device__ __forceinline__ void mma_f16(float* d, const uint32_t* a, const uint32_t* b) {
    asm volatile(
        "mma.sync.aligned.m16n8k16.row.col.f32.f16.f16.f32 "
        "{%0,%1,%2,%3}, {%4,%5,%6,%7}, {%8,%9}, {%0,%1,%2,%3};"
        : "+f"(d[0]), "+f"(d[1]), "+f"(d[2]), "+f"(d[3])
        : "r"(a[0]), "r"(a[1]), "r"(a[2]), "r"(a[3]), "r"(b[0]), "r"(b[1]));
}
__device__ __forceinline__ uint32_t sw128(uint32_t off) {
    return off ^ ((off >> 3) & 0x70);
}

// ---------------- fused row/col partial sums (one adj pass) ------------------
// Tile: 128 rows x 256 cols per CTA (128KB, fits L1 for the second phase).
__global__ __launch_bounds__(256, 1)
void rowcol_kernel(const float* __restrict__ adj,
                   float* __restrict__ rowpart, float* __restrict__ colpart) {
    int cb = blockIdx.x;          // 0..31
    int rb = blockIdx.y;          // 0..63
    int c = cb * 256 + threadIdx.x;
    int r0 = rb * 128;
    float s = 0.f;
    #pragma unroll 8
    for (int r = r0; r < r0 + 128; r++) s += adj[(size_t)r * NROWS + c];
    colpart[(size_t)rb * NROWS + c] = s;
    if (threadIdx.x < 128) {
        int r = r0 + threadIdx.x;
        const float4* rp = (const float4*)(adj + (size_t)r * NROWS + cb * 256);
        float t = 0.f;
        #pragma unroll 8
        for (int i = 0; i < 64; i++) {
            float4 v = rp[i];
            t += (v.x + v.y) + (v.z + v.w);
        }
        rowpart[(size_t)cb * NROWS + r] = t;
    }
}

// drow/dcol = 64 * sum^-0.5 (64*64 = 4096 fp16 range scaling folded in)
__global__ void dscale_kernel(const float* __restrict__ rowpart, const float* __restrict__ colpart,
                              float* __restrict__ drow, float* __restrict__ dcol) {
    int i = blockIdx.x * 256 + threadIdx.x;
    float rs = 0.f;
    #pragma unroll
    for (int p = 0; p < 32; p++) rs += rowpart[(size_t)p * NROWS + i];
    drow[i] = rs > 0.f ? 64.0f * rsqrtf(rs) : 0.f;
    float cs = 0.f;
    #pragma unroll
    for (int p = 0; p < 64; p++) cs += colpart[(size_t)p * NROWS + i];
    dcol[i] = cs > 0.f ? 64.0f * rsqrtf(cs) : 0.f;
}

// ---------------- Ps = 4096 * drow∘adj∘dcol -> fp16 -------------------------
__global__ void convert_adj(const float* __restrict__ adj,
                            const float* __restrict__ drow, const float* __restrict__ dcol,
                            __half* __restrict__ ps) {
    size_t i4 = (size_t)blockIdx.x * 256 + threadIdx.x;   // over 8192*2048 float4s
    int row = (int)(i4 >> 11);
    int c4  = (int)(i4 & 2047);
    float4 v = ((const float4*)adj)[i4];
    float dr = drow[row];
    float4 dc = ((const float4*)dcol)[c4];
    __half2 h0 = __floats2half2_rn(dr * v.x * dc.x, dr * v.y * dc.y);
    __half2 h1 = __floats2half2_rn(dr * v.z * dc.z, dr * v.w * dc.w);
    uint2 o;
    o.x = *(uint32_t*)&h0;
    o.y = *(uint32_t*)&h1;
    ((uint2*)ps)[i4] = o;
}

// ---------------- x -> fp16 --------------------------------------------------
__global__ void convert_x(const float* __restrict__ x, __half* __restrict__ xh) {
    size_t i4 = (size_t)blockIdx.x * 256 + threadIdx.x;   // over 8192*128 float4s
    float4 v = ((const float4*)x)[i4];
    __half2 h0 = __floats2half2_rn(v.x, v.y);
    __half2 h1 = __floats2half2_rn(v.z, v.w);
    uint2 o;
    o.x = *(uint32_t*)&h0;
    o.y = *(uint32_t*)&h1;
    ((uint2*)xh)[i4] = o;
}

// ---------------- transpose + fp16 hi/lo split -------------------------------
// src [gridDim.x*32][gridDim.y*32(+...)] row-major with row stride srcN,
// dst [srcN][dstStride], dstStride = gridDim.x*32.
__global__ void trans_split(const float* __restrict__ src,
                            __half* __restrict__ hi, __half* __restrict__ lo, int srcN) {
    __shared__ float tile[32][33];
    int m0 = blockIdx.x * 32, n0 = blockIdx.y * 32;
    int dstStride = gridDim.x * 32;
    int tx = threadIdx.x, ty = threadIdx.y;   // 32 x 8
    #pragma unroll
    for (int j = 0; j < 4; j++)
        tile[ty + j * 8][tx] = src[(size_t)(m0 + ty + j * 8) * srcN + n0 + tx];
    __syncthreads();
    #pragma unroll
    for (int j = 0; j < 4; j++) {
        int n = n0 + ty + j * 8;
        float v = tile[tx][ty + j * 8];
        __half h = __float2half_rn(v);
        __half l = __float2half_rn(v - __half2float(h));
        size_t o = (size_t)n * dstStride + m0 + tx;
        hi[o] = h;
        lo[o] = l;
    }
}

// ---------------- HMMA GEMM: C[64x256/CTA] = A_f16 @ (Bhi+Blo)^T ------------
// BM=64, BN=256, BK=64, 2-stage cp.async, SW128 smem, 8 warps (2M x 4N).
#define GK 64
#define STG_A  8192                     // 64 rows * 128B
#define STG_B  32768                    // 256 rows * 128B
#define STG_BYTES (STG_A + 2*STG_B)     // 73728
#define GEMM_SMEM (2 * STG_BYTES)       // 147456

__global__ __launch_bounds__(256, 1)
void gemm2p(const __half* __restrict__ A_g,
            const __half* __restrict__ Bhi_g, const __half* __restrict__ Blo_g,
            float* __restrict__ C, int K, float descale) {
    extern __shared__ __align__(1024) char smem[];
    const int tid = threadIdx.x, lane = tid & 31, wid = tid >> 5;
    const int wm = wid >> 2;          // 0..1
    const int wn = wid & 3;           // 0..3
    const int blockM = blockIdx.x * 64;
    const uint32_t sbase = smem_u32(smem);

    const __half* A = A_g + (size_t)blockM * K;

    float d[2][8][4];
    #pragma unroll
    for (int mt = 0; mt < 2; mt++)
        #pragma unroll
        for (int nt = 0; nt < 8; nt++)
            #pragma unroll
            for (int e = 0; e < 4; e++) d[mt][nt][e] = 0.f;

    auto load_stage = [&](int it, uint32_t stg) {
        int k0 = it * GK;
        #pragma unroll
        for (int idx = tid; idx < 512; idx += 256) {
            int row = idx >> 3, g = idx & 7;
            cp16(stg + sw128((uint32_t)(row * 128 + g * 16)),
                 A + (size_t)row * K + k0 + g * 8);
        }
        #pragma unroll
        for (int idx = tid; idx < 2048; idx += 256) {
            int row = idx >> 3, g = idx & 7;
            cp16(stg + STG_A + sw128((uint32_t)(row * 128 + g * 16)),
                 Bhi_g + (size_t)row * K + k0 + g * 8);
        }
        #pragma unroll
        for (int idx = tid; idx < 2048; idx += 256) {
            int row = idx >> 3, g = idx & 7;
            cp16(stg + STG_A + STG_B + sw128((uint32_t)(row * 128 + g * 16)),
                 Blo_g + (size_t)row * K + k0 + g * 8);
        }
    };

    const int rowA = wm * 32 + (lane & 15);
    const int kbA  = (lane >> 4) * 16;
    const int rowB = wn * 64 + (lane & 7) + ((lane >> 4) & 1) * 8;
    const int kbB  = ((lane >> 3) & 1) * 16;

    const int NIT = K / GK;
    load_stage(0, sbase);
    CP_COMMIT();

    for (int it = 0; it < NIT; ++it) {
        uint32_t stg = sbase + (uint32_t)(it & 1) * STG_BYTES;
        if (it + 1 < NIT) {
            load_stage(it + 1, sbase + (uint32_t)((it + 1) & 1) * STG_BYTES);
            CP_COMMIT();
            CP_WAIT(1);
        } else {
            CP_WAIT(0);
        }
        __syncthreads();

        const uint32_t sA = stg;
        const uint32_t sBhi = stg + STG_A, sBlo = stg + STG_A + STG_B;

        #pragma unroll
        for (int ks = 0; ks < 4; ks++) {
            uint32_t a[2][4];
            #pragma unroll
            for (int mt = 0; mt < 2; mt++) {
                uint32_t off = sw128((uint32_t)((rowA + mt * 16) * 128 + ks * 32 + kbA));
                ldmx4(a[mt][0], a[mt][1], a[mt][2], a[mt][3], sA + off);
            }
            uint32_t bh[8][2], bl[8][2];
            #pragma unroll
            for (int p = 0; p < 4; p++) {
                uint32_t off = sw128((uint32_t)((rowB + p * 16) * 128 + ks * 32 + kbB));
                ldmx4(bh[2*p][0], bh[2*p][1], bh[2*p+1][0], bh[2*p+1][1], sBhi + off);
                ldmx4(bl[2*p][0], bl[2*p][1], bl[2*p+1][0], bl[2*p+1][1], sBlo + off);
            }
            #pragma unroll
            for (int mt = 0; mt < 2; mt++)
                #pragma unroll
                for (int nt = 0; nt < 8; nt++) {
                    mma_f16(d[mt][nt], a[mt], bh[nt]);
                    mma_f16(d[mt][nt], a[mt], bl[nt]);
                }
        }
        __syncthreads();
    }

    const int q = lane >> 2, c2 = (lane & 3) * 2;
    #pragma unroll
    for (int mt = 0; mt < 2; mt++) {
        int m0 = blockM + wm * 32 + mt * 16 + q;
        #pragma unroll
        for (int nt = 0; nt < 8; nt++) {
            int col = wn * 64 + nt * 8 + c2;
            *(float2*)&C[(size_t)m0 * NHIDD + col] =
                make_float2(d[mt][nt][0] * descale, d[mt][nt][1] * descale);
            *(float2*)&C[(size_t)(m0 + 8) * NHIDD + col] =
                make_float2(d[mt][nt][2] * descale, d[mt][nt][3] * descale);
        }
    }
}

// ---------------- layer-1 epilogue + Z = H@W2 fused -------------------------
__global__ void epi2_kernel(const float* __restrict__ ACC, const float* __restrict__ X1,
                            const float* __restrict__ T1, const float* __restrict__ W2,
                            float2* __restrict__ Z) {
    int warp = threadIdx.x >> 5, lane = threadIdx.x & 31;
    int row = blockIdx.x * 8 + warp;
    size_t base = (size_t)row * NHIDD;
    float z0 = 0.f, z1 = 0.f;
    #pragma unroll
    for (int b = 0; b < 2; b++) {
        int n0 = lane * 8 + b * 4;
        float4 av = *(const float4*)&ACC[base + n0];
        float4 xv = *(const float4*)&X1[base + n0];
        float4 tv = *(const float4*)&T1[base + n0];
        float as[4] = {av.x, av.y, av.z, av.w};
        float xs[4] = {xv.x, xv.y, xv.z, xv.w};
        float ts[4] = {tv.x, tv.y, tv.z, tv.w};
        #pragma unroll
        for (int e = 0; e < 4; e++) {
            float h = 0.5f * xs[e] - 0.5f * ts[e] - as[e];
            h = h > 0.f ? h : 0.f;
            int n = n0 + e;
            z0 = fmaf(h, W2[2 * n], z0);
            z1 = fmaf(h, W2[2 * n + 1], z1);
        }
    }
    #pragma unroll
    for (int o = 16; o > 0; o >>= 1) {
        z0 += __shfl_xor_sync(0xffffffffu, z0, o);
        z1 += __shfl_xor_sync(0xffffffffu, z1, o);
    }
    if (lane == 0) Z[row] = make_float2(z0, z1);
}

// ---------------- U = (Ps @ V) * DESCALE, V [8192,2] (fp16 matvec) ----------
// FINAL=1 fuses the log_softmax epilogue.
template<int FINAL>
__global__ void pv16(const __half* __restrict__ Ps, const float2* __restrict__ V,
                     const float2* __restrict__ Z, const float2* __restrict__ U1,
                     const float* __restrict__ b2,
                     float2* __restrict__ outU, float* __restrict__ out) {
    int warp = threadIdx.x >> 5, lane = threadIdx.x & 31;
    int row = blockIdx.x * 8 + warp;
    const uint4* ap = (const uint4*)(Ps + (size_t)row * NROWS);
    float ax = 0.f, ay = 0.f;
    for (int i = lane; i < NROWS / 8; i += 32) {
        uint4 q = ap[i];
        float2 f0 = __half22float2(*(__half2*)&q.x);
        float2 f1 = __half22float2(*(__half2*)&q.y);
        float2 f2 = __half22float2(*(__half2*)&q.z);
        float2 f3 = __half22float2(*(__half2*)&q.w);
        int k = i * 8;
        float2 v0 = V[k],     v1 = V[k + 1], v2 = V[k + 2], v3 = V[k + 3];
        float2 v4 = V[k + 4], v5 = V[k + 5], v6 = V[k + 6], v7 = V[k + 7];
        ax += f0.x * v0.x + f0.y * v1.x + f1.x * v2.x + f1.y * v3.x
            + f2.x * v4.x + f2.y * v5.x + f3.x * v6.x + f3.y * v7.x;
        ay += f0.x * v0.y + f0.y * v1.y + f1.x * v2.y + f1.y * v3.y
            + f2.x * v4.y + f2.y * v5.y + f3.x * v6.y + f3.y * v7.y;
    }
    #pragma unroll
    for (int o = 16; o > 0; o >>= 1) {
        ax += __shfl_xor_sync(0xffffffffu, ax, o);
        ay += __shfl_xor_sync(0xffffffffu, ay, o);
    }
    if (lane == 0) {
        float ux = ax * DESCALE, uy = ay * DESCALE;
        if (FINAL == 0) {
            outU[row] = make_float2(ux, uy);
        } else {
            float2 z = Z[row];
            float2 u1 = U1[row];
            float l0 = 0.5f * z.x - 0.5f * u1.x - ux + b2[0];
            float l1 = 0.5f * z.y - 0.5f * u1.y - uy + b2[1];
            float mx = fmaxf(l0, l1);
            float lse = mx + logf(expf(l0 - mx) + expf(l1 - mx));
            out[2 * row + 0] = l0 - lse;
            out[2 * row + 1] = l1 - lse;
        }
    }
}

// ---------------- launcher --------------------------------------------------
extern "C" void kernel_launch(void* const* d_in, const int* in_sizes, int n_in,
                              void* d_out, int out_size) {
    const float* x   = (const float*)d_in[0];
    const float* adj = (const float*)d_in[1];
    const float* W1  = (const float*)d_in[2];
    const float* W2  = (const float*)d_in[3];
    const float* b2  = (const float*)d_in[4];
    float* out = (float*)d_out;

    float *rowpart, *colpart, *drow, *dcol, *X1, *T1, *ACC;
    __half *Ps, *xh, *W1Thi, *W1Tlo, *Bt1hi, *Bt1lo, *Bt2hi, *Bt2lo;
    float2 *Z, *U1;
    cudaGetSymbolAddress((void**)&rowpart, g_rowpart);
    cudaGetSymbolAddress((void**)&colpart, g_colpart);
    cudaGetSymbolAddress((void**)&drow,    g_drow);
    cudaGetSymbolAddress((void**)&dcol,    g_dcol);
    cudaGetSymbolAddress((void**)&X1,      g_X1);
    cudaGetSymbolAddress((void**)&T1,      g_T1);
    cudaGetSymbolAddress((void**)&ACC,     g_ACC);
    cudaGetSymbolAddress((void**)&Ps,      g_Ps);
    cudaGetSymbolAddress((void**)&xh,      g_xh);
    cudaGetSymbolAddress((void**)&W1Thi,   g_W1Thi);
    cudaGetSymbolAddress((void**)&W1Tlo,   g_W1Tlo);
    cudaGetSymbolAddress((void**)&Bt1hi,   g_Bt1hi);
    cudaGetSymbolAddress((void**)&Bt1lo,   g_Bt1lo);
    cudaGetSymbolAddress((void**)&Bt2hi,   g_Bt2hi);
    cudaGetSymbolAddress((void**)&Bt2lo,   g_Bt2lo);
    cudaGetSymbolAddress((void**)&Z,       g_Z);
    cudaGetSymbolAddress((void**)&U1,      g_U1);

    cudaFuncSetAttribute(gemm2p, cudaFuncAttributeMaxDynamicSharedMemorySize, GEMM_SMEM);

    // degree sums (one adj pass) -> drow/dcol (with *64 fp16-range scaling)
    rowcol_kernel<<<dim3(32, 64), 256>>>(adj, rowpart, colpart);
    dscale_kernel<<<NROWS / 256, 256>>>(rowpart, colpart, drow, dcol);

    // conversions
    convert_adj<<<(NROWS * (NROWS / 4)) / 256, 256>>>(adj, drow, dcol, Ps);
    convert_x<<<(NROWS * (NFEATD / 4)) / 256, 256>>>(x, xh);
    trans_split<<<dim3(NFEATD / 32, NHIDD / 32), dim3(32, 8)>>>(W1, W1Thi, W1Tlo, NHIDD);

    // X1 = x @ W1 (HMMA, K=512)
    gemm2p<<<NROWS / 64, 256, GEMM_SMEM>>>(xh, W1Thi, W1Tlo, X1, NFEATD, 1.0f);

    // Bt1 = X1^T hi/lo
    trans_split<<<dim3(NROWS / 32, NHIDD / 32), dim3(32, 8)>>>(X1, Bt1hi, Bt1lo, NHIDD);

    // T1 = P @ X1 (HMMA, K=8192, descale 1/4096)
    gemm2p<<<NROWS / 64, 256, GEMM_SMEM>>>(Ps, Bt1hi, Bt1lo, T1, NROWS, DESCALE);

    // Bt2 = T1^T hi/lo
    trans_split<<<dim3(NROWS / 32, NHIDD / 32), dim3(32, 8)>>>(T1, Bt2hi, Bt2lo, NHIDD);

    // ACC = P @ T1
    gemm2p<<<NROWS / 64, 256, GEMM_SMEM>>>(Ps, Bt2hi, Bt2lo, ACC, NROWS, DESCALE);

    // H = relu(0.5*X1 - 0.5*T1 - ACC); Z = H@W2
    epi2_kernel<<<NROWS / 8, 256>>>(ACC, X1, T1, W2, Z);

    // U1 = P @ Z
    pv16<0><<<NROWS / 8, 256>>>(Ps, Z, nullptr, nullptr, nullptr, U1, nullptr);

    // out = log_softmax(0.5*Z - 0.5*U1 - P@U1 + b2)
    pv16<1><<<NROWS / 8, 256>>>(Ps, U1, Z, U1, b2, nullptr, out);
}

// round 5
// speedup vs baseline: 3.3870x; 1.2215x over previous
#include <cuda_runtime.h>
#include <cuda_fp16.h>
#include <math.h>
#include <stdint.h>

// MidGCN on GB300 (compute_103 PTX => mma.sync fp16 HMMA):
//   adj_f = 0.5*I - 0.5*P - P^2,  P = drow ∘ adj ∘ dcol
//   layer1: H = relu(0.5*X1 - 0.5*T1 - P@T1),  X1 = x@W1, T1 = P@X1
//   layer2: out = log_softmax(0.5*Z - 0.5*(P@Z) - P@(P@Z) + b2), Z = H@W2
// Big GEMMs: single-product fp16 HMMA (error budget validated: ~1.5e-4 total).
// P pre-scaled by 4096 (64*64 folded into drow/dcol) for fp16 range.

#define NROWS 8192
#define NHIDD 256
#define NFEATD 512
#define DESCALE (1.0f / 4096.0f)

// ---------------- scratch (device globals) ----------------------------------
__device__ float g_rowpart[32 * NROWS];
__device__ float g_colpart[64 * NROWS];
__device__ float g_drow[NROWS];
__device__ float g_dcol[NROWS];
__device__ float g_X1[NROWS * NHIDD];
__device__ float g_T1[NROWS * NHIDD];
__device__ float g_ACC[NROWS * NHIDD];
__device__ __half g_Ps[(size_t)NROWS * NROWS];     // P * 4096, fp16
__device__ __half g_xh[NROWS * NFEATD];            // x fp16
__device__ __half g_W1Thi[NHIDD * NFEATD];         // W1^T hi/lo
__device__ __half g_W1Tlo[NHIDD * NFEATD];
__device__ __half g_Bt1hi[NHIDD * NROWS];          // X1^T fp16
__device__ __half g_Bt2hi[NHIDD * NROWS];          // T1^T fp16
__device__ float2 g_Z [NROWS];
__device__ float2 g_U1[NROWS];

// ---------------- helpers ----------------------------------------------------
__device__ __forceinline__ uint32_t smem_u32(const void* p) {
    return (uint32_t)__cvta_generic_to_shared(p);
}
__device__ __forceinline__ void cp16(uint32_t s, const void* g) {
    asm volatile("cp.async.cg.shared.global [%0], [%1], 16;"
                 :: "r"(s), "l"(__cvta_generic_to_global(g)) : "memory");
}
#define CP_COMMIT() asm volatile("cp.async.commit_group;" ::: "memory")
#define CP_WAIT(n)  asm volatile("cp.async.wait_group %0;" :: "n"(n) : "memory")

__device__ __forceinline__ void ldmx4(uint32_t& r0, uint32_t& r1, uint32_t& r2, uint32_t& r3,
                                      uint32_t addr) {
    asm volatile("ldmatrix.sync.aligned.m8n8.x4.shared.b16 {%0,%1,%2,%3}, [%4];"
                 : "=r"(r0), "=r"(r1), "=r"(r2), "=r"(r3) : "r"(addr));
}
__device__ __forceinline__ void mma_f16(float* d, const uint32_t* a, const uint32_t* b) {
    asm volatile(
        "mma.sync.aligned.m16n8k16.row.col.f32.f16.f16.f32 "
        "{%0,%1,%2,%3}, {%4,%5,%6,%7}, {%8,%9}, {%0,%1,%2,%3};"
        : "+f"(d[0]), "+f"(d[1]), "+f"(d[2]), "+f"(d[3])
        : "r"(a[0]), "r"(a[1]), "r"(a[2]), "r"(a[3]), "r"(b[0]), "r"(b[1]));
}
__device__ __forceinline__ uint32_t sw128(uint32_t off) {
    return off ^ ((off >> 3) & 0x70);
}

// ---------------- fused row/col partial sums (one adj pass) ------------------
__global__ __launch_bounds__(256, 1)
void rowcol_kernel(const float* __restrict__ adj,
                   float* __restrict__ rowpart, float* __restrict__ colpart) {
    int cb = blockIdx.x;          // 0..31
    int rb = blockIdx.y;          // 0..63
    int c = cb * 256 + threadIdx.x;
    int r0 = rb * 128;
    float s = 0.f;
    #pragma unroll 8
    for (int r = r0; r < r0 + 128; r++) s += adj[(size_t)r * NROWS + c];
    colpart[(size_t)rb * NROWS + c] = s;
    if (threadIdx.x < 128) {
        int r = r0 + threadIdx.x;
        const float4* rp = (const float4*)(adj + (size_t)r * NROWS + cb * 256);
        float t = 0.f;
        #pragma unroll 8
        for (int i = 0; i < 64; i++) {
            float4 v = rp[i];
            t += (v.x + v.y) + (v.z + v.w);
        }
        rowpart[(size_t)cb * NROWS + r] = t;
    }
}

// drow/dcol = 64 * sum^-0.5 (64*64 = 4096 fp16 range scaling folded in)
__global__ void dscale_kernel(const float* __restrict__ rowpart, const float* __restrict__ colpart,
                              float* __restrict__ drow, float* __restrict__ dcol) {
    int i = blockIdx.x * 256 + threadIdx.x;
    float rs = 0.f;
    #pragma unroll
    for (int p = 0; p < 32; p++) rs += rowpart[(size_t)p * NROWS + i];
    drow[i] = rs > 0.f ? 64.0f * rsqrtf(rs) : 0.f;
    float cs = 0.f;
    #pragma unroll
    for (int p = 0; p < 64; p++) cs += colpart[(size_t)p * NROWS + i];
    dcol[i] = cs > 0.f ? 64.0f * rsqrtf(cs) : 0.f;
}

// ---------------- Ps = 4096 * drow∘adj∘dcol -> fp16 -------------------------
__global__ void convert_adj(const float* __restrict__ adj,
                            const float* __restrict__ drow, const float* __restrict__ dcol,
                            __half* __restrict__ ps) {
    size_t i4 = (size_t)blockIdx.x * 256 + threadIdx.x;
    int row = (int)(i4 >> 11);
    int c4  = (int)(i4 & 2047);
    float4 v = ((const float4*)adj)[i4];
    float dr = drow[row];
    float4 dc = ((const float4*)dcol)[c4];
    __half2 h0 = __floats2half2_rn(dr * v.x * dc.x, dr * v.y * dc.y);
    __half2 h1 = __floats2half2_rn(dr * v.z * dc.z, dr * v.w * dc.w);
    uint2 o;
    o.x = *(uint32_t*)&h0;
    o.y = *(uint32_t*)&h1;
    ((uint2*)ps)[i4] = o;
}

// ---------------- x -> fp16 --------------------------------------------------
__global__ void convert_x(const float* __restrict__ x, __half* __restrict__ xh) {
    size_t i4 = (size_t)blockIdx.x * 256 + threadIdx.x;
    float4 v = ((const float4*)x)[i4];
    __half2 h0 = __floats2half2_rn(v.x, v.y);
    __half2 h1 = __floats2half2_rn(v.z, v.w);
    uint2 o;
    o.x = *(uint32_t*)&h0;
    o.y = *(uint32_t*)&h1;
    ((uint2*)xh)[i4] = o;
}

// ---------------- transpose + fp16 split (optionally hi only) ----------------
template<bool WRITE_LO>
__global__ void trans_split(const float* __restrict__ src,
                            __half* __restrict__ hi, __half* __restrict__ lo, int srcN) {
    __shared__ float tile[32][33];
    int m0 = blockIdx.x * 32, n0 = blockIdx.y * 32;
    int dstStride = gridDim.x * 32;
    int tx = threadIdx.x, ty = threadIdx.y;   // 32 x 8
    #pragma unroll
    for (int j = 0; j < 4; j++)
        tile[ty + j * 8][tx] = src[(size_t)(m0 + ty + j * 8) * srcN + n0 + tx];
    __syncthreads();
    #pragma unroll
    for (int j = 0; j < 4; j++) {
        int n = n0 + ty + j * 8;
        float v = tile[tx][ty + j * 8];
        __half h = __float2half_rn(v);
        size_t o = (size_t)n * dstStride + m0 + tx;
        hi[o] = h;
        if (WRITE_LO) lo[o] = __float2half_rn(v - __half2float(h));
    }
}

// ---------------- HMMA GEMM: C[128x128/CTA] = A_f16 @ (Bhi [+ Blo])^T -------
// BM=128, BN=128, BK=64, 3-stage cp.async, SW128 smem, 8 warps (4M x 2N),
// warp tile 32x64.
#define GK 64
#define TILE_BYTES 16384                 // 128 rows * 128B

template<int NPROD>
__global__ __launch_bounds__(256, 1)
void gemmNP(const __half* __restrict__ A_g,
            const __half* __restrict__ Bhi_g, const __half* __restrict__ Blo_g,
            float* __restrict__ C, int K, float descale) {
    const int STAGE = TILE_BYTES * (1 + NPROD);
    extern __shared__ __align__(1024) char smem[];
    const int tid = threadIdx.x, lane = tid & 31, wid = tid >> 5;
    const int wm = wid >> 1;          // 0..3
    const int wn = wid & 1;           // 0..1
    const int blockM = blockIdx.x * 128;
    const int blockN = blockIdx.y * 128;
    const uint32_t sbase = smem_u32(smem);

    const __half* A   = A_g   + (size_t)blockM * K;
    const __half* Bhi = Bhi_g + (size_t)blockN * K;
    const __half* Blo = (NPROD == 2) ? Blo_g + (size_t)blockN * K : nullptr;

    float d[2][8][4];
    #pragma unroll
    for (int mt = 0; mt < 2; mt++)
        #pragma unroll
        for (int nt = 0; nt < 8; nt++)
            #pragma unroll
            for (int e = 0; e < 4; e++) d[mt][nt][e] = 0.f;

    auto load_stage = [&](int it, int buf) {
        uint32_t stg = sbase + (uint32_t)buf * STAGE;
        int k0 = it * GK;
        #pragma unroll
        for (int idx = tid; idx < 1024; idx += 256) {
            int row = idx >> 3, g = idx & 7;
            cp16(stg + sw128((uint32_t)(row * 128 + g * 16)),
                 A + (size_t)row * K + k0 + g * 8);
        }
        #pragma unroll
        for (int idx = tid; idx < 1024; idx += 256) {
            int row = idx >> 3, g = idx & 7;
            cp16(stg + TILE_BYTES + sw128((uint32_t)(row * 128 + g * 16)),
                 Bhi + (size_t)row * K + k0 + g * 8);
        }
        if (NPROD == 2) {
            #pragma unroll
            for (int idx = tid; idx < 1024; idx += 256) {
                int row = idx >> 3, g = idx & 7;
                cp16(stg + 2 * TILE_BYTES + sw128((uint32_t)(row * 128 + g * 16)),
                     Blo + (size_t)row * K + k0 + g * 8);
            }
        }
        CP_COMMIT();
    };

    const int rowA = wm * 32 + (lane & 15);
    const int kbA  = (lane >> 4) * 16;
    const int rowB = wn * 64 + (lane & 7) + ((lane >> 4) & 1) * 8;
    const int kbB  = ((lane >> 3) & 1) * 16;

    const int NIT = K / GK;
    load_stage(0, 0);
    load_stage(1, 1);

    for (int it = 0; it < NIT; ++it) {
        if (it + 2 < NIT) { load_stage(it + 2, (it + 2) % 3); CP_WAIT(2); }
        else if (it + 1 < NIT) { CP_WAIT(1); }
        else { CP_WAIT(0); }
        __syncthreads();

        uint32_t stg = sbase + (uint32_t)(it % 3) * STAGE;
        const uint32_t sA = stg;
        const uint32_t sBhi = stg + TILE_BYTES;
        const uint32_t sBlo = stg + 2 * TILE_BYTES;

        #pragma unroll
        for (int ks = 0; ks < 4; ks++) {
            uint32_t a[2][4];
            #pragma unroll
            for (int mt = 0; mt < 2; mt++) {
                uint32_t off = sw128((uint32_t)((rowA + mt * 16) * 128 + ks * 32 + kbA));
                ldmx4(a[mt][0], a[mt][1], a[mt][2], a[mt][3], sA + off);
            }
            uint32_t bh[8][2];
            #pragma unroll
            for (int p = 0; p < 4; p++) {
                uint32_t off = sw128((uint32_t)((rowB + p * 16) * 128 + ks * 32 + kbB));
                ldmx4(bh[2*p][0], bh[2*p][1], bh[2*p+1][0], bh[2*p+1][1], sBhi + off);
            }
            #pragma unroll
            for (int mt = 0; mt < 2; mt++)
                #pragma unroll
                for (int nt = 0; nt < 8; nt++)
                    mma_f16(d[mt][nt], a[mt], bh[nt]);
            if (NPROD == 2) {
                uint32_t bl[8][2];
                #pragma unroll
                for (int p = 0; p < 4; p++) {
                    uint32_t off = sw128((uint32_t)((rowB + p * 16) * 128 + ks * 32 + kbB));
                    ldmx4(bl[2*p][0], bl[2*p][1], bl[2*p+1][0], bl[2*p+1][1], sBlo + off);
                }
                #pragma unroll
                for (int mt = 0; mt < 2; mt++)
                    #pragma unroll
                    for (int nt = 0; nt < 8; nt++)
                        mma_f16(d[mt][nt], a[mt], bl[nt]);
            }
        }
        __syncthreads();
    }

    const int q = lane >> 2, c2 = (lane & 3) * 2;
    #pragma unroll
    for (int mt = 0; mt < 2; mt++) {
        int m0 = blockM + wm * 32 + mt * 16 + q;
        #pragma unroll
        for (int nt = 0; nt < 8; nt++) {
            int col = blockN + wn * 64 + nt * 8 + c2;
            *(float2*)&C[(size_t)m0 * NHIDD + col] =
                make_float2(d[mt][nt][0] * descale, d[mt][nt][1] * descale);
            *(float2*)&C[(size_t)(m0 + 8) * NHIDD + col] =
                make_float2(d[mt][nt][2] * descale, d[mt][nt][3] * descale);
        }
    }
}

// ---------------- layer-1 epilogue + Z = H@W2 fused -------------------------
__global__ void epi2_kernel(const float* __restrict__ ACC, const float* __restrict__ X1,
                            const float* __restrict__ T1, const float* __restrict__ W2,
                            float2* __restrict__ Z) {
    int warp = threadIdx.x >> 5, lane = threadIdx.x & 31;
    int row = blockIdx.x * 8 + warp;
    size_t base = (size_t)row * NHIDD;
    float z0 = 0.f, z1 = 0.f;
    #pragma unroll
    for (int b = 0; b < 2; b++) {
        int n0 = lane * 8 + b * 4;
        float4 av = *(const float4*)&ACC[base + n0];
        float4 xv = *(const float4*)&X1[base + n0];
        float4 tv = *(const float4*)&T1[base + n0];
        float as[4] = {av.x, av.y, av.z, av.w};
        float xs[4] = {xv.x, xv.y, xv.z, xv.w};
        float ts[4] = {tv.x, tv.y, tv.z, tv.w};
        #pragma unroll
        for (int e = 0; e < 4; e++) {
            float h = 0.5f * xs[e] - 0.5f * ts[e] - as[e];
            h = h > 0.f ? h : 0.f;
            int n = n0 + e;
            z0 = fmaf(h, W2[2 * n], z0);
            z1 = fmaf(h, W2[2 * n + 1], z1);
        }
    }
    #pragma unroll
    for (int o = 16; o > 0; o >>= 1) {
        z0 += __shfl_xor_sync(0xffffffffu, z0, o);
        z1 += __shfl_xor_sync(0xffffffffu, z1, o);
    }
    if (lane == 0) Z[row] = make_float2(z0, z1);
}

// ---------------- U = (Ps @ V) * DESCALE, V [8192,2] ------------------------
template<int FINAL>
__global__ void pv16(const __half* __restrict__ Ps, const float2* __restrict__ V,
                     const float2* __restrict__ Z, const float2* __restrict__ U1,
                     const float* __restrict__ b2,
                     float2* __restrict__ outU, float* __restrict__ out) {
    int warp = threadIdx.x >> 5, lane = threadIdx.x & 31;
    int row = blockIdx.x * 8 + warp;
    const uint4* ap = (const uint4*)(Ps + (size_t)row * NROWS);
    float ax = 0.f, ay = 0.f;
    for (int i = lane; i < NROWS / 8; i += 32) {
        uint4 q = ap[i];
        float2 f0 = __half22float2(*(__half2*)&q.x);
        float2 f1 = __half22float2(*(__half2*)&q.y);
        float2 f2 = __half22float2(*(__half2*)&q.z);
        float2 f3 = __half22float2(*(__half2*)&q.w);
        int k = i * 8;
        float2 v0 = V[k],     v1 = V[k + 1], v2 = V[k + 2], v3 = V[k + 3];
        float2 v4 = V[k + 4], v5 = V[k + 5], v6 = V[k + 6], v7 = V[k + 7];
        ax += f0.x * v0.x + f0.y * v1.x + f1.x * v2.x + f1.y * v3.x
            + f2.x * v4.x + f2.y * v5.x + f3.x * v6.x + f3.y * v7.x;
        ay += f0.x * v0.y + f0.y * v1.y + f1.x * v2.y + f1.y * v3.y
            + f2.x * v4.y + f2.y * v5.y + f3.x * v6.y + f3.y * v7.y;
    }
    #pragma unroll
    for (int o = 16; o > 0; o >>= 1) {
        ax += __shfl_xor_sync(0xffffffffu, ax, o);
        ay += __shfl_xor_sync(0xffffffffu, ay, o);
    }
    if (lane == 0) {
        float ux = ax * DESCALE, uy = ay * DESCALE;
        if (FINAL == 0) {
            outU[row] = make_float2(ux, uy);
        } else {
            float2 z = Z[row];
            float2 u1 = U1[row];
            float l0 = 0.5f * z.x - 0.5f * u1.x - ux + b2[0];
            float l1 = 0.5f * z.y - 0.5f * u1.y - uy + b2[1];
            float mx = fmaxf(l0, l1);
            float lse = mx + logf(expf(l0 - mx) + expf(l1 - mx));
            out[2 * row + 0] = l0 - lse;
            out[2 * row + 1] = l1 - lse;
        }
    }
}

// ---------------- launcher --------------------------------------------------
extern "C" void kernel_launch(void* const* d_in, const int* in_sizes, int n_in,
                              void* d_out, int out_size) {
    const float* x   = (const float*)d_in[0];
    const float* adj = (const float*)d_in[1];
    const float* W1  = (const float*)d_in[2];
    const float* W2  = (const float*)d_in[3];
    const float* b2  = (const float*)d_in[4];
    float* out = (float*)d_out;

    float *rowpart, *colpart, *drow, *dcol, *X1, *T1, *ACC;
    __half *Ps, *xh, *W1Thi, *W1Tlo, *Bt1hi, *Bt2hi;
    float2 *Z, *U1;
    cudaGetSymbolAddress((void**)&rowpart, g_rowpart);
    cudaGetSymbolAddress((void**)&colpart, g_colpart);
    cudaGetSymbolAddress((void**)&drow,    g_drow);
    cudaGetSymbolAddress((void**)&dcol,    g_dcol);
    cudaGetSymbolAddress((void**)&X1,      g_X1);
    cudaGetSymbolAddress((void**)&T1,      g_T1);
    cudaGetSymbolAddress((void**)&ACC,     g_ACC);
    cudaGetSymbolAddress((void**)&Ps,      g_Ps);
    cudaGetSymbolAddress((void**)&xh,      g_xh);
    cudaGetSymbolAddress((void**)&W1Thi,   g_W1Thi);
    cudaGetSymbolAddress((void**)&W1Tlo,   g_W1Tlo);
    cudaGetSymbolAddress((void**)&Bt1hi,   g_Bt1hi);
    cudaGetSymbolAddress((void**)&Bt2hi,   g_Bt2hi);
    cudaGetSymbolAddress((void**)&Z,       g_Z);
    cudaGetSymbolAddress((void**)&U1,      g_U1);

    const int SM1 = 3 * TILE_BYTES * 2;   // gemmNP<1>: 98304
    const int SM2 = 3 * TILE_BYTES * 3;   // gemmNP<2>: 147456
    cudaFuncSetAttribute(gemmNP<1>, cudaFuncAttributeMaxDynamicSharedMemorySize, SM1);
    cudaFuncSetAttribute(gemmNP<2>, cudaFuncAttributeMaxDynamicSharedMemorySize, SM2);

    // degree sums (one adj pass) -> drow/dcol (with *64 fp16-range scaling)
    rowcol_kernel<<<dim3(32, 64), 256>>>(adj, rowpart, colpart);
    dscale_kernel<<<NROWS / 256, 256>>>(rowpart, colpart, drow, dcol);

    // conversions
    convert_adj<<<(NROWS * (NROWS / 4)) / 256, 256>>>(adj, drow, dcol, Ps);
    convert_x<<<(NROWS * (NFEATD / 4)) / 256, 256>>>(x, xh);
    trans_split<true><<<dim3(NFEATD / 32, NHIDD / 32), dim3(32, 8)>>>(W1, W1Thi, W1Tlo, NHIDD);

    // X1 = x @ W1 (2-product, K=512)
    gemmNP<2><<<dim3(NROWS / 128, NHIDD / 128), 256, SM2>>>(xh, W1Thi, W1Tlo, X1, NFEATD, 1.0f);

    // Bt1 = X1^T fp16
    trans_split<false><<<dim3(NROWS / 32, NHIDD / 32), dim3(32, 8)>>>(X1, Bt1hi, nullptr, NHIDD);

    // T1 = P @ X1 (single-product, K=8192)
    gemmNP<1><<<dim3(NROWS / 128, NHIDD / 128), 256, SM1>>>(Ps, Bt1hi, nullptr, T1, NROWS, DESCALE);

    // Bt2 = T1^T fp16
    trans_split<false><<<dim3(NROWS / 32, NHIDD / 32), dim3(32, 8)>>>(T1, Bt2hi, nullptr, NHIDD);

    // ACC = P @ T1 (single-product)
    gemmNP<1><<<dim3(NROWS / 128, NHIDD / 128), 256, SM1>>>(Ps, Bt2hi, nullptr, ACC, NROWS, DESCALE);

    // H = relu(0.5*X1 - 0.5*T1 - ACC); Z = H@W2
    epi2_kernel<<<NROWS / 8, 256>>>(ACC, X1, T1, W2, Z);

    // U1 = P @ Z
    pv16<0><<<NROWS / 8, 256>>>(Ps, Z, nullptr, nullptr, nullptr, U1, nullptr);

    // out = log_softmax(0.5*Z - 0.5*U1 - P@U1 + b2)
    pv16<1><<<NROWS / 8, 256>>>(Ps, U1, Z, U1, b2, nullptr, out);
}